// round 1
// baseline (speedup 1.0000x reference)
#include <cuda_runtime.h>
#include <math.h>
#include <stdint.h>

// Problem constants
#define NN 50000
#define EE 320000
constexpr int DN   = 256;  // node feature dim / out dim (H*C)
constexpr int DEF  = 128;  // raw edge feature dim
constexpr int TD   = 64;   // time encoder dim
constexpr int DEIN = 192;  // TD + DEF
constexpr int H    = 8;
constexpr int CH   = 32;   // per-head dim

// ---------------- scratch (device globals; no allocation allowed) ----------
__device__ float    g_Q[(size_t)NN * DN];
__device__ float    g_K[(size_t)NN * DN];
__device__ float    g_V[(size_t)NN * DN];
__device__ float    g_ep[(size_t)EE * DN];       // 327 MB
__device__ float    g_alpha[(size_t)EE * H];     // alpha, then exp(alpha-m) in place
__device__ unsigned g_m[(size_t)NN * H];         // monotone-encoded float max
__device__ float    g_denom[(size_t)NN * H];
__device__ float    g_tfeat[(size_t)EE * TD];

// monotone float <-> uint mapping so atomicMax(unsigned) == float max
__device__ __forceinline__ unsigned f2u_mono(float f) {
    unsigned u = __float_as_uint(f);
    return (u & 0x80000000u) ? ~u : (u | 0x80000000u);
}
__device__ __forceinline__ float u2f_mono(unsigned u) {
    u = (u & 0x80000000u) ? (u & 0x7fffffffu) : ~u;
    return __uint_as_float(u);
}

__device__ __forceinline__ void red_add_v4(float* p, float4 v) {
    asm volatile("red.global.add.v4.f32 [%0], {%1,%2,%3,%4};"
                 :: "l"(p), "f"(v.x), "f"(v.y), "f"(v.z), "f"(v.w) : "memory");
}

// ---------------- K0: per-launch zero init (graph replay safe) -------------
__global__ void k_init() {
    int i = blockIdx.x * blockDim.x + threadIdx.x;
    if (i < NN * H) { g_m[i] = 0u; g_denom[i] = 0.0f; }
}

// ---------------- K_time: tfeat = cos(t*w + b) ------------------------------
__global__ void k_time(const float* __restrict__ t,
                       const float* __restrict__ w,
                       const float* __restrict__ b) {
    int idx = blockIdx.x * blockDim.x + threadIdx.x;
    if (idx >= EE * TD) return;
    int e = idx >> 6;
    int i = idx & 63;
    g_tfeat[idx] = cosf(t[e] * w[i] + b[i]);
}

// ---------------- K1: fused node GEMMs (Q,K,V + skip into out) --------------
// Y = X @ W^T + bias, treated as M=50000, Nout=1024 (4 matrices x 256), K=256
__global__ __launch_bounds__(256)
void k_node_gemm(const float* __restrict__ X,
                 const float* __restrict__ Wq, const float* __restrict__ Wk,
                 const float* __restrict__ Wv, const float* __restrict__ Ws,
                 const float* __restrict__ bq, const float* __restrict__ bk,
                 const float* __restrict__ bv, const float* __restrict__ bs,
                 float* __restrict__ out) {
    constexpr int BM = 128, BN = 128, BK = 32;
    __shared__ float As[BK][BM + 4];
    __shared__ float Bs[BK][BN + 4];

    int by  = blockIdx.y;            // 0..7
    int mat = by >> 1;
    int n0  = (by & 1) * BN;         // col offset inside the 256-wide matrix
    const float* W; const float* bias; float* dst;
    if      (mat == 0) { W = Wq; bias = bq; dst = g_Q; }
    else if (mat == 1) { W = Wk; bias = bk; dst = g_K; }
    else if (mat == 2) { W = Wv; bias = bv; dst = g_V; }
    else               { W = Ws; bias = bs; dst = out; }

    int m0  = blockIdx.x * BM;
    int tid = threadIdx.x;
    int tx  = tid & 15, ty = tid >> 4;

    float acc[8][8] = {};

    for (int k0 = 0; k0 < DN; k0 += BK) {
        // load A tile (X[m0..m0+128, k0..k0+32]) transposed into As[k][m]
#pragma unroll
        for (int q = 0; q < 4; q++) {
            int idx = tid + 256 * q;
            int r = idx >> 3, c4 = idx & 7;
            int node = m0 + r;
            float4 v = make_float4(0.f, 0.f, 0.f, 0.f);
            if (node < NN) v = *(const float4*)&X[(size_t)node * DN + k0 + c4 * 4];
            As[c4 * 4 + 0][r] = v.x; As[c4 * 4 + 1][r] = v.y;
            As[c4 * 4 + 2][r] = v.z; As[c4 * 4 + 3][r] = v.w;
        }
        // load B tile (W[n0..n0+128, k0..k0+32]) into Bs[k][n]
#pragma unroll
        for (int q = 0; q < 4; q++) {
            int idx = tid + 256 * q;
            int r = idx >> 3, c4 = idx & 7;
            float4 v = *(const float4*)&W[(size_t)(n0 + r) * DN + k0 + c4 * 4];
            Bs[c4 * 4 + 0][r] = v.x; Bs[c4 * 4 + 1][r] = v.y;
            Bs[c4 * 4 + 2][r] = v.z; Bs[c4 * 4 + 3][r] = v.w;
        }
        __syncthreads();
#pragma unroll
        for (int kk = 0; kk < BK; kk++) {
            float a[8], b8[8];
            *(float4*)&a[0]  = *(const float4*)&As[kk][ty * 8];
            *(float4*)&a[4]  = *(const float4*)&As[kk][ty * 8 + 4];
            *(float4*)&b8[0] = *(const float4*)&Bs[kk][tx * 8];
            *(float4*)&b8[4] = *(const float4*)&Bs[kk][tx * 8 + 4];
#pragma unroll
            for (int i = 0; i < 8; i++)
#pragma unroll
                for (int j = 0; j < 8; j++) acc[i][j] += a[i] * b8[j];
        }
        __syncthreads();
    }

    float bb[8];
#pragma unroll
    for (int j = 0; j < 8; j++) bb[j] = bias[n0 + tx * 8 + j];

#pragma unroll
    for (int i = 0; i < 8; i++) {
        int node = m0 + ty * 8 + i;
        if (node < NN) {
            float4 w1 = make_float4(acc[i][0] + bb[0], acc[i][1] + bb[1],
                                    acc[i][2] + bb[2], acc[i][3] + bb[3]);
            float4 w2 = make_float4(acc[i][4] + bb[4], acc[i][5] + bb[5],
                                    acc[i][6] + bb[6], acc[i][7] + bb[7]);
            float4* dp = (float4*)&dst[(size_t)node * DN + n0 + tx * 8];
            dp[0] = w1; dp[1] = w2;
        }
    }
}

// ---------------- K2: edge GEMM ep = e_attr @ We^T, alpha + segment max -----
__global__ __launch_bounds__(256)
void k_edge(const float* __restrict__ edge_feats,
            const int* __restrict__ etup,
            const float* __restrict__ We) {
    constexpr int BM = 128, BN = 128, BK = 32;
    __shared__ float As[BK][BM + 4];
    __shared__ float Bs[BK][BN + 4];

    int e0 = blockIdx.x * BM;
    int n0 = blockIdx.y * BN;    // 0 or 128 -> heads 0..3 or 4..7
    int tid = threadIdx.x;
    int tx = tid & 15, ty = tid >> 4;

    float acc[8][8] = {};

    for (int k0 = 0; k0 < DEIN; k0 += BK) {
        const float* base; int stride; int coff;
        if (k0 < TD) { base = g_tfeat;    stride = TD;  coff = k0; }
        else         { base = edge_feats; stride = DEF; coff = k0 - TD; }
#pragma unroll
        for (int q = 0; q < 4; q++) {
            int idx = tid + 256 * q;
            int r = idx >> 3, c4 = idx & 7;
            float4 v = *(const float4*)&base[(size_t)(e0 + r) * stride + coff + c4 * 4];
            As[c4 * 4 + 0][r] = v.x; As[c4 * 4 + 1][r] = v.y;
            As[c4 * 4 + 2][r] = v.z; As[c4 * 4 + 3][r] = v.w;
        }
#pragma unroll
        for (int q = 0; q < 4; q++) {
            int idx = tid + 256 * q;
            int r = idx >> 3, c4 = idx & 7;
            float4 v = *(const float4*)&We[(size_t)(n0 + r) * DEIN + k0 + c4 * 4];
            Bs[c4 * 4 + 0][r] = v.x; Bs[c4 * 4 + 1][r] = v.y;
            Bs[c4 * 4 + 2][r] = v.z; Bs[c4 * 4 + 3][r] = v.w;
        }
        __syncthreads();
#pragma unroll
        for (int kk = 0; kk < BK; kk++) {
            float a[8], b8[8];
            *(float4*)&a[0]  = *(const float4*)&As[kk][ty * 8];
            *(float4*)&a[4]  = *(const float4*)&As[kk][ty * 8 + 4];
            *(float4*)&b8[0] = *(const float4*)&Bs[kk][tx * 8];
            *(float4*)&b8[4] = *(const float4*)&Bs[kk][tx * 8 + 4];
#pragma unroll
            for (int i = 0; i < 8; i++)
#pragma unroll
                for (int j = 0; j < 8; j++) acc[i][j] += a[i] * b8[j];
        }
        __syncthreads();
    }

    // write ep tile
#pragma unroll
    for (int i = 0; i < 8; i++) {
        int e = e0 + ty * 8 + i;
        float4* dp = (float4*)&g_ep[(size_t)e * DN + n0 + tx * 8];
        dp[0] = make_float4(acc[i][0], acc[i][1], acc[i][2], acc[i][3]);
        dp[1] = make_float4(acc[i][4], acc[i][5], acc[i][6], acc[i][7]);
    }

    // alpha = q[dst] . (k[src] + ep) / sqrt(32); 4 lanes (tx%4 group) per head
    const float scale = 0.17677669529663687f;  // 1/sqrt(32)
    int head = (n0 >> 5) + (tx >> 2);          // global head id for this thread
#pragma unroll
    for (int i = 0; i < 8; i++) {
        int e = e0 + ty * 8 + i;
        int s = etup[e];
        int d = etup[EE + e];
        const float* qr = &g_Q[(size_t)d * DN + n0 + tx * 8];
        const float* kr = &g_K[(size_t)s * DN + n0 + tx * 8];
        float4 q1 = *(const float4*)qr,       q2 = *(const float4*)(qr + 4);
        float4 k1 = *(const float4*)kr,       k2 = *(const float4*)(kr + 4);
        float p = q1.x * (k1.x + acc[i][0]) + q1.y * (k1.y + acc[i][1])
                + q1.z * (k1.z + acc[i][2]) + q1.w * (k1.w + acc[i][3])
                + q2.x * (k2.x + acc[i][4]) + q2.y * (k2.y + acc[i][5])
                + q2.z * (k2.z + acc[i][6]) + q2.w * (k2.w + acc[i][7]);
        p += __shfl_xor_sync(0xffffffffu, p, 1, 4);
        p += __shfl_xor_sync(0xffffffffu, p, 2, 4);
        if ((tx & 3) == 0) {
            float a = p * scale;
            g_alpha[(size_t)e * H + head] = a;
            atomicMax(&g_m[d * H + head], f2u_mono(a));
        }
    }
}

// ---------------- K3: ea = exp(alpha - m[dst]); denom += ea -----------------
__global__ void k_softmax(const int* __restrict__ etup) {
    int idx = blockIdx.x * blockDim.x + threadIdx.x;
    if (idx >= EE * H) return;
    int e = idx >> 3;
    int h = idx & 7;
    int d = etup[EE + e];
    float m  = u2f_mono(g_m[d * H + h]);
    float ea = __expf(g_alpha[idx] - m);
    g_alpha[idx] = ea;
    atomicAdd(&g_denom[d * H + h], ea);
}

// ---------------- K4: out[dst] += a * (v[src] + ep)  (warp per edge) --------
__global__ __launch_bounds__(256)
void k_aggregate(const int* __restrict__ etup, float* __restrict__ out) {
    int gw = (blockIdx.x * blockDim.x + threadIdx.x) >> 5;
    if (gw >= EE) return;
    int lane = threadIdx.x & 31;
    int e = gw;
    int s = etup[e];
    int d = etup[EE + e];

    int h0 = lane >> 3;          // cols lane*4      -> head 0..3
    int h1 = 4 + (lane >> 3);    // cols 128+lane*4  -> head 4..7
    float a0 = g_alpha[(size_t)e * H + h0] / (g_denom[d * H + h0] + 1e-16f);
    float a1 = g_alpha[(size_t)e * H + h1] / (g_denom[d * H + h1] + 1e-16f);

    int c0 = lane * 4;
    int c1 = 128 + lane * 4;
    float4 v0 = *(const float4*)&g_V[(size_t)s * DN + c0];
    float4 p0 = *(const float4*)&g_ep[(size_t)e * DN + c0];
    float4 v1 = *(const float4*)&g_V[(size_t)s * DN + c1];
    float4 p1 = *(const float4*)&g_ep[(size_t)e * DN + c1];

    float4 r0 = make_float4(a0 * (v0.x + p0.x), a0 * (v0.y + p0.y),
                            a0 * (v0.z + p0.z), a0 * (v0.w + p0.w));
    float4 r1 = make_float4(a1 * (v1.x + p1.x), a1 * (v1.y + p1.y),
                            a1 * (v1.z + p1.z), a1 * (v1.w + p1.w));
    red_add_v4(&out[(size_t)d * DN + c0], r0);
    red_add_v4(&out[(size_t)d * DN + c1], r1);
}

// ---------------- launch ----------------------------------------------------
extern "C" void kernel_launch(void* const* d_in, const int* in_sizes, int n_in,
                              void* d_out, int out_size) {
    const int*   etup       = (const int*)  d_in[0];   // [2, E]
    const float* edge_feats = (const float*)d_in[1];   // [E, 128]
    const float* times      = (const float*)d_in[2];   // [E]
    const float* X          = (const float*)d_in[3];   // [N, 256]
    const float* w_time     = (const float*)d_in[4];   // [64]
    const float* b_time     = (const float*)d_in[5];   // [64]
    const float* Wq         = (const float*)d_in[6];
    const float* bq         = (const float*)d_in[7];
    const float* Wk         = (const float*)d_in[8];
    const float* bk         = (const float*)d_in[9];
    const float* Wv         = (const float*)d_in[10];
    const float* bv         = (const float*)d_in[11];
    const float* We         = (const float*)d_in[12];  // [256, 192]
    const float* Ws         = (const float*)d_in[13];
    const float* bs         = (const float*)d_in[14];
    float* out = (float*)d_out;

    k_init<<<(NN * H + 255) / 256, 256>>>();
    k_time<<<(EE * TD) / 256, 256>>>(times, w_time, b_time);
    k_node_gemm<<<dim3((NN + 127) / 128, 8), 256>>>(X, Wq, Wk, Wv, Ws,
                                                    bq, bk, bv, bs, out);
    k_edge<<<dim3(EE / 128, 2), 256>>>(edge_feats, etup, We);
    k_softmax<<<(EE * H) / 256, 256>>>(etup);
    k_aggregate<<<EE / 8, 256>>>(etup, out);
}

// round 3
// speedup vs baseline: 1.7224x; 1.7224x over previous
#include <cuda_runtime.h>
#include <math.h>
#include <stdint.h>

#define NN 50000
#define EE 320000
constexpr int DN   = 256;
constexpr int DEF  = 128;
constexpr int TD   = 64;
constexpr int DEIN = 192;
constexpr int H    = 8;

// ---------------- scratch ---------------------------------------------------
__device__ float    g_Q[(size_t)NN * DN];
__device__ float    g_K[(size_t)NN * DN];
__device__ float    g_V[(size_t)NN * DN];
__device__ float    g_ep[(size_t)EE * DN];
__device__ float    g_alpha[(size_t)EE * H];
__device__ unsigned g_m[(size_t)NN * H];
__device__ float    g_denom[(size_t)NN * H];

// ---------------- helpers ---------------------------------------------------
__device__ __forceinline__ unsigned f2u_mono(float f) {
    unsigned u = __float_as_uint(f);
    return (u & 0x80000000u) ? ~u : (u | 0x80000000u);
}
__device__ __forceinline__ float u2f_mono(unsigned u) {
    u = (u & 0x80000000u) ? (u & 0x7fffffffu) : ~u;
    return __uint_as_float(u);
}
__device__ __forceinline__ void red_add_v4(float* p, float4 v) {
    asm volatile("red.global.add.v4.f32 [%0], {%1,%2,%3,%4};"
                 :: "l"(p), "f"(v.x), "f"(v.y), "f"(v.z), "f"(v.w) : "memory");
}
__device__ __forceinline__ uint32_t f2tf32(float f) {
    uint32_t r; asm("cvt.rna.tf32.f32 %0, %1;" : "=r"(r) : "f"(f)); return r;
}
__device__ __forceinline__ void mma_tf32(float* c, const uint32_t* a, const uint32_t* b) {
    asm volatile(
        "mma.sync.aligned.m16n8k8.row.col.f32.tf32.tf32.f32 "
        "{%0,%1,%2,%3}, {%4,%5,%6,%7}, {%8,%9}, {%0,%1,%2,%3};"
        : "+f"(c[0]), "+f"(c[1]), "+f"(c[2]), "+f"(c[3])
        : "r"(a[0]), "r"(a[1]), "r"(a[2]), "r"(a[3]), "r"(b[0]), "r"(b[1]));
}

// ---------------- smem layout -----------------------------------------------
// sT(512) sW(256) sB(256) | A0(16K) A1(16K) B0(16K) B1(16K)
constexpr int SM_T  = 0;
constexpr int SM_W  = 512;
constexpr int SM_BT = 768;
constexpr int SM_A0 = 1024;
constexpr int SM_A1 = SM_A0 + 16384;
constexpr int SM_B0 = SM_A1 + 16384;
constexpr int SM_B1 = SM_B0 + 16384;
constexpr int SMEM_BYTES = SM_B1 + 16384;  // 66560

// Fragment-layout staging indices.
// A tile 128(m) x 32(k):  sA[((ks*8 + mt)*32 + lane)*4 + ri]
//   mt=m>>4, r=m&15, ks=kk>>3, lane=(r&7)*4+(kk&3), ri=(r>>3)+2*((kk>>2)&1)
// B tile 128(n) x 32(k):  sB[((ks*16 + nt)*32 + lane)*2 + ri]
//   nt=n>>3, lane=(n&7)*4+(kk&3), ri=(kk>>2)&1
__device__ __forceinline__ void putA(uint32_t* sA, int row, int kk, float v) {
    int r = row & 15, mt = row >> 4, ks = kk >> 3;
    int ln = (r & 7) * 4 + (kk & 3);
    int ri = (r >> 3) + 2 * ((kk >> 2) & 1);
    sA[((ks * 8 + mt) * 32 + ln) * 4 + ri] = f2tf32(v);
}
__device__ __forceinline__ void putB(uint32_t* sB, int n, int kk, float v) {
    int nt = n >> 3, ks = kk >> 3;
    int ln = (n & 7) * 4 + (kk & 3);
    int ri = (kk >> 2) & 1;
    sB[((ks * 16 + nt) * 32 + ln) * 2 + ri] = f2tf32(v);
}

__device__ __forceinline__ void stage_B_w(uint32_t* sB, const float* __restrict__ W,
                                          int n0, int k0, int stride) {
    int tid = threadIdx.x;
#pragma unroll
    for (int i = 0; i < 4; i++) {
        int id = tid + 256 * i;            // 128 rows x 8 float4
        int n = id >> 3, c4 = id & 7;
        float4 v = *(const float4*)&W[(size_t)(n0 + n) * stride + k0 + c4 * 4];
        putB(sB, n, c4 * 4 + 0, v.x); putB(sB, n, c4 * 4 + 1, v.y);
        putB(sB, n, c4 * 4 + 2, v.z); putB(sB, n, c4 * 4 + 3, v.w);
    }
}

__device__ __forceinline__ void stage_A_node(uint32_t* sA, const float* __restrict__ X,
                                             int m0, int k0) {
    int tid = threadIdx.x;
#pragma unroll
    for (int i = 0; i < 4; i++) {
        int id = tid + 256 * i;
        int row = id >> 3, c4 = id & 7;
        int node = m0 + row;
        float4 v = make_float4(0.f, 0.f, 0.f, 0.f);
        if (node < NN) v = *(const float4*)&X[(size_t)node * DN + k0 + c4 * 4];
        putA(sA, row, c4 * 4 + 0, v.x); putA(sA, row, c4 * 4 + 1, v.y);
        putA(sA, row, c4 * 4 + 2, v.z); putA(sA, row, c4 * 4 + 3, v.w);
    }
}

__device__ __forceinline__ void stage_A_edge(uint32_t* sA, const char* smem,
                                             const float* __restrict__ ef,
                                             int e0, int c) {
    int tid = threadIdx.x;
    if (c < 2) {  // time-encoder cols: cos(t*w+b)
        const float* sT = (const float*)(smem + SM_T);
        const float* sW = (const float*)(smem + SM_W);
        const float* sBt = (const float*)(smem + SM_BT);
        int k0 = c * 32;
#pragma unroll
        for (int i = 0; i < 16; i++) {
            int id = tid + 256 * i;        // 128 rows x 32 cols
            int row = id >> 5, kk = id & 31;
            float v = cosf(sT[row] * sW[k0 + kk] + sBt[k0 + kk]);
            putA(sA, row, kk, v);
        }
    } else {
        int k0 = c * 32 - 64;
#pragma unroll
        for (int i = 0; i < 4; i++) {
            int id = tid + 256 * i;
            int row = id >> 3, c4 = id & 7;
            float4 v = *(const float4*)&ef[(size_t)(e0 + row) * DEF + k0 + c4 * 4];
            putA(sA, row, c4 * 4 + 0, v.x); putA(sA, row, c4 * 4 + 1, v.y);
            putA(sA, row, c4 * 4 + 2, v.z); putA(sA, row, c4 * 4 + 3, v.w);
        }
    }
}

// compute one 32-K chunk: warp tile 32x64, acc[2][8][4]
__device__ __forceinline__ void chunk_mma(const uint32_t* sA, const uint32_t* sB,
                                          int warpM, int warpN, int lane,
                                          float acc[2][8][4]) {
#pragma unroll
    for (int ks = 0; ks < 4; ks++) {
        uint32_t af[2][4];
#pragma unroll
        for (int m = 0; m < 2; m++)
            *(uint4*)af[m] = *(const uint4*)&sA[((ks * 8 + warpM * 2 + m) * 32 + lane) * 4];
        uint32_t bf[8][2];
#pragma unroll
        for (int j = 0; j < 8; j++)
            *(uint2*)bf[j] = *(const uint2*)&sB[((ks * 16 + warpN * 8 + j) * 32 + lane) * 2];
#pragma unroll
        for (int m = 0; m < 2; m++)
#pragma unroll
            for (int j = 0; j < 8; j++) mma_tf32(acc[m][j], af[m], bf[j]);
    }
}

// ---------------- K0: per-launch zero init ----------------------------------
__global__ void k_init() {
    int i = blockIdx.x * blockDim.x + threadIdx.x;
    if (i < NN * H) { g_m[i] = 0u; g_denom[i] = 0.0f; }
}

// ---------------- node GEMMs: Q,K,V,skip ------------------------------------
__global__ __launch_bounds__(256, 2)
void k_node_mma(const float* __restrict__ X,
                const float* __restrict__ Wq, const float* __restrict__ Wk,
                const float* __restrict__ Wv, const float* __restrict__ Ws,
                const float* __restrict__ bq, const float* __restrict__ bk,
                const float* __restrict__ bv, const float* __restrict__ bs,
                float* __restrict__ out) {
    extern __shared__ char smem[];
    const int tid = threadIdx.x, wid = tid >> 5, lane = tid & 31;
    const int warpM = wid & 3, warpN = wid >> 2;
    const int m0 = blockIdx.x * 128;
    const int by = blockIdx.y, mat = by >> 1, n0 = (by & 1) * 128;
    const float* W; const float* bias; float* dst;
    if      (mat == 0) { W = Wq; bias = bq; dst = g_Q; }
    else if (mat == 1) { W = Wk; bias = bk; dst = g_K; }
    else if (mat == 2) { W = Wv; bias = bv; dst = g_V; }
    else               { W = Ws; bias = bs; dst = out; }

    uint32_t* sA[2] = { (uint32_t*)(smem + SM_A0), (uint32_t*)(smem + SM_A1) };
    uint32_t* sB[2] = { (uint32_t*)(smem + SM_B0), (uint32_t*)(smem + SM_B1) };

    float acc[2][8][4] = {};

    stage_A_node(sA[0], X, m0, 0);
    stage_B_w(sB[0], W, n0, 0, DN);
    __syncthreads();

    for (int c = 0; c < 8; c++) {
        chunk_mma(sA[c & 1], sB[c & 1], warpM, warpN, lane, acc);
        if (c < 7) {
            stage_A_node(sA[(c + 1) & 1], X, m0, (c + 1) * 32);
            stage_B_w(sB[(c + 1) & 1], W, n0, (c + 1) * 32, DN);
        }
        __syncthreads();
    }

    // epilogue: bias + store
    float2 bb[8];
#pragma unroll
    for (int j = 0; j < 8; j++)
        bb[j] = *(const float2*)&bias[n0 + warpN * 64 + j * 8 + (lane & 3) * 2];
#pragma unroll
    for (int m = 0; m < 2; m++)
#pragma unroll
        for (int rv = 0; rv < 2; rv++) {
            int node = m0 + warpM * 32 + m * 16 + rv * 8 + (lane >> 2);
            if (node >= NN) continue;
            float* dp = dst + (size_t)node * DN + n0 + warpN * 64 + (lane & 3) * 2;
#pragma unroll
            for (int j = 0; j < 8; j++) {
                float2 o = make_float2(acc[m][j][rv * 2 + 0] + bb[j].x,
                                       acc[m][j][rv * 2 + 1] + bb[j].y);
                *(float2*)(dp + j * 8) = o;
            }
        }
}

// ---------------- edge GEMM + fused time-enc + fused alpha ------------------
__global__ __launch_bounds__(256, 2)
void k_edge_mma(const float* __restrict__ ef, const int* __restrict__ etup,
                const float* __restrict__ We, const float* __restrict__ times,
                const float* __restrict__ wt, const float* __restrict__ bt) {
    extern __shared__ char smem[];
    const int tid = threadIdx.x, wid = tid >> 5, lane = tid & 31;
    const int warpM = wid & 3, warpN = wid >> 2;
    const int e0 = blockIdx.x * 128;
    const int n0 = blockIdx.y * 128;

    if (tid < 128) ((float*)(smem + SM_T))[tid] = times[e0 + tid];
    if (tid < 64) {
        ((float*)(smem + SM_W))[tid]  = wt[tid];
        ((float*)(smem + SM_BT))[tid] = bt[tid];
    }
    __syncthreads();

    uint32_t* sA[2] = { (uint32_t*)(smem + SM_A0), (uint32_t*)(smem + SM_A1) };
    uint32_t* sB[2] = { (uint32_t*)(smem + SM_B0), (uint32_t*)(smem + SM_B1) };

    float acc[2][8][4] = {};

    stage_A_edge(sA[0], smem, ef, e0, 0);
    stage_B_w(sB[0], We, n0, 0, DEIN);
    __syncthreads();

    for (int c = 0; c < 6; c++) {
        chunk_mma(sA[c & 1], sB[c & 1], warpM, warpN, lane, acc);
        if (c < 5) {
            stage_A_edge(sA[(c + 1) & 1], smem, ef, e0, c + 1);
            stage_B_w(sB[(c + 1) & 1], We, n0, (c + 1) * 32, DEIN);
        }
        __syncthreads();
    }

    // epilogue: store ep, alpha = q[dst].(k[src]+ep)/sqrt(32), segment max
    const float scale = 0.17677669529663687f;
    const int headbase = (n0 + warpN * 64) >> 5;
#pragma unroll
    for (int m = 0; m < 2; m++)
#pragma unroll
        for (int rv = 0; rv < 2; rv++) {
            int e = e0 + warpM * 32 + m * 16 + rv * 8 + (lane >> 2);
            int s = etup[e];
            int d = etup[EE + e];
            const float* qrow = g_Q + (size_t)d * DN + n0 + warpN * 64 + (lane & 3) * 2;
            const float* krow = g_K + (size_t)s * DN + n0 + warpN * 64 + (lane & 3) * 2;
            float* dp = g_ep + (size_t)e * DN + n0 + warpN * 64 + (lane & 3) * 2;
            float p0 = 0.f, p1 = 0.f;
#pragma unroll
            for (int j = 0; j < 8; j++) {
                float c0 = acc[m][j][rv * 2 + 0];
                float c1 = acc[m][j][rv * 2 + 1];
                *(float2*)(dp + j * 8) = make_float2(c0, c1);
                float2 qv = *(const float2*)(qrow + j * 8);
                float2 kv = *(const float2*)(krow + j * 8);
                float p = qv.x * (kv.x + c0) + qv.y * (kv.y + c1);
                if (j < 4) p0 += p; else p1 += p;
            }
            p0 += __shfl_xor_sync(0xffffffffu, p0, 1);
            p0 += __shfl_xor_sync(0xffffffffu, p0, 2);
            p1 += __shfl_xor_sync(0xffffffffu, p1, 1);
            p1 += __shfl_xor_sync(0xffffffffu, p1, 2);
            if ((lane & 3) == 0) {
                float a0 = p0 * scale, a1 = p1 * scale;
                g_alpha[(size_t)e * H + headbase]     = a0;
                g_alpha[(size_t)e * H + headbase + 1] = a1;
                atomicMax(&g_m[d * H + headbase],     f2u_mono(a0));
                atomicMax(&g_m[d * H + headbase + 1], f2u_mono(a1));
            }
        }
}

// ---------------- K3: ea = exp(alpha - m[dst]); denom += ea -----------------
__global__ void k_softmax(const int* __restrict__ etup) {
    int idx = blockIdx.x * blockDim.x + threadIdx.x;
    if (idx >= EE * H) return;
    int e = idx >> 3;
    int h = idx & 7;
    int d = etup[EE + e];
    float m  = u2f_mono(g_m[d * H + h]);
    float ea = __expf(g_alpha[idx] - m);
    g_alpha[idx] = ea;
    atomicAdd(&g_denom[d * H + h], ea);
}

// ---------------- K4: out[dst] += a * (v[src] + ep) -------------------------
__global__ __launch_bounds__(256)
void k_aggregate(const int* __restrict__ etup, float* __restrict__ out) {
    int gw = (blockIdx.x * blockDim.x + threadIdx.x) >> 5;
    if (gw >= EE) return;
    int lane = threadIdx.x & 31;
    int e = gw;
    int s = etup[e];
    int d = etup[EE + e];

    int h0 = lane >> 3;
    int h1 = 4 + (lane >> 3);
    float a0 = g_alpha[(size_t)e * H + h0] / (g_denom[d * H + h0] + 1e-16f);
    float a1 = g_alpha[(size_t)e * H + h1] / (g_denom[d * H + h1] + 1e-16f);

    int c0 = lane * 4;
    int c1 = 128 + lane * 4;
    float4 v0 = *(const float4*)&g_V[(size_t)s * DN + c0];
    float4 p0 = *(const float4*)&g_ep[(size_t)e * DN + c0];
    float4 v1 = *(const float4*)&g_V[(size_t)s * DN + c1];
    float4 p1 = *(const float4*)&g_ep[(size_t)e * DN + c1];

    float4 r0 = make_float4(a0 * (v0.x + p0.x), a0 * (v0.y + p0.y),
                            a0 * (v0.z + p0.z), a0 * (v0.w + p0.w));
    float4 r1 = make_float4(a1 * (v1.x + p1.x), a1 * (v1.y + p1.y),
                            a1 * (v1.z + p1.z), a1 * (v1.w + p1.w));
    red_add_v4(&out[(size_t)d * DN + c0], r0);
    red_add_v4(&out[(size_t)d * DN + c1], r1);
}

// ---------------- launch ----------------------------------------------------
extern "C" void kernel_launch(void* const* d_in, const int* in_sizes, int n_in,
                              void* d_out, int out_size) {
    const int*   etup       = (const int*)  d_in[0];
    const float* edge_feats = (const float*)d_in[1];
    const float* times      = (const float*)d_in[2];
    const float* X          = (const float*)d_in[3];
    const float* w_time     = (const float*)d_in[4];
    const float* b_time     = (const float*)d_in[5];
    const float* Wq         = (const float*)d_in[6];
    const float* bq         = (const float*)d_in[7];
    const float* Wk         = (const float*)d_in[8];
    const float* bk         = (const float*)d_in[9];
    const float* Wv         = (const float*)d_in[10];
    const float* bv         = (const float*)d_in[11];
    const float* We         = (const float*)d_in[12];
    const float* Ws         = (const float*)d_in[13];
    const float* bs         = (const float*)d_in[14];
    float* out = (float*)d_out;

    cudaFuncSetAttribute(k_node_mma, cudaFuncAttributeMaxDynamicSharedMemorySize, SMEM_BYTES);
    cudaFuncSetAttribute(k_edge_mma, cudaFuncAttributeMaxDynamicSharedMemorySize, SMEM_BYTES);

    k_init<<<(NN * H + 255) / 256, 256>>>();
    k_node_mma<<<dim3((NN + 127) / 128, 8), 256, SMEM_BYTES>>>(
        X, Wq, Wk, Wv, Ws, bq, bk, bv, bs, out);
    k_edge_mma<<<dim3(EE / 128, 2), 256, SMEM_BYTES>>>(
        edge_feats, etup, We, times, w_time, b_time);
    k_softmax<<<(EE * H) / 256, 256>>>(etup);
    k_aggregate<<<EE / 8, 256>>>(etup, out);
}

// round 4
// speedup vs baseline: 1.8699x; 1.0856x over previous
#include <cuda_runtime.h>
#include <math.h>
#include <stdint.h>

#define NN 50000
#define EE 320000
constexpr int DN   = 256;
constexpr int DEF  = 128;
constexpr int TD   = 64;
constexpr int DEIN = 192;
constexpr int H    = 8;

// ---------------- scratch ---------------------------------------------------
__device__ float g_Q[(size_t)NN * DN];
__device__ float g_K[(size_t)NN * DN];
__device__ float g_V[(size_t)NN * DN];
__device__ float g_acc[(size_t)NN * DN];    // unnormalized numerator
__device__ float g_denom[(size_t)NN * H];   // unnormalized softmax denom

// ---------------- helpers ---------------------------------------------------
__device__ __forceinline__ void red_add_v2(float* p, float2 v) {
    asm volatile("red.global.add.v2.f32 [%0], {%1,%2};"
                 :: "l"(p), "f"(v.x), "f"(v.y) : "memory");
}
__device__ __forceinline__ void red_add_f(float* p, float v) {
    asm volatile("red.global.add.f32 [%0], %1;" :: "l"(p), "f"(v) : "memory");
}
__device__ __forceinline__ uint32_t f2tf32(float f) {
    uint32_t r; asm("cvt.rna.tf32.f32 %0, %1;" : "=r"(r) : "f"(f)); return r;
}
__device__ __forceinline__ void mma_tf32(float* c, const uint32_t* a, const uint32_t* b) {
    asm volatile(
        "mma.sync.aligned.m16n8k8.row.col.f32.tf32.tf32.f32 "
        "{%0,%1,%2,%3}, {%4,%5,%6,%7}, {%8,%9}, {%0,%1,%2,%3};"
        : "+f"(c[0]), "+f"(c[1]), "+f"(c[2]), "+f"(c[3])
        : "r"(a[0]), "r"(a[1]), "r"(a[2]), "r"(a[3]), "r"(b[0]), "r"(b[1]));
}

// ---------------- smem layout -----------------------------------------------
constexpr int SM_T  = 0;
constexpr int SM_W  = 512;
constexpr int SM_BT = 768;
constexpr int SM_A0 = 1024;
constexpr int SM_A1 = SM_A0 + 16384;
constexpr int SM_B0 = SM_A1 + 16384;
constexpr int SM_B1 = SM_B0 + 16384;
constexpr int SMEM_BYTES = SM_B1 + 16384;  // 66560

// Fragment-layout staging (same as R3)
__device__ __forceinline__ void putA(uint32_t* sA, int row, int kk, float v) {
    int r = row & 15, mt = row >> 4, ks = kk >> 3;
    int ln = (r & 7) * 4 + (kk & 3);
    int ri = (r >> 3) + 2 * ((kk >> 2) & 1);
    sA[((ks * 8 + mt) * 32 + ln) * 4 + ri] = f2tf32(v);
}
__device__ __forceinline__ void putB(uint32_t* sB, int n, int kk, float v) {
    int nt = n >> 3, ks = kk >> 3;
    int ln = (n & 7) * 4 + (kk & 3);
    int ri = (kk >> 2) & 1;
    sB[((ks * 16 + nt) * 32 + ln) * 2 + ri] = f2tf32(v);
}

__device__ __forceinline__ void stage_B_w(uint32_t* sB, const float* __restrict__ W,
                                          int n0, int k0, int stride) {
    int tid = threadIdx.x;
#pragma unroll
    for (int i = 0; i < 4; i++) {
        int id = tid + 256 * i;
        int n = id >> 3, c4 = id & 7;
        float4 v = *(const float4*)&W[(size_t)(n0 + n) * stride + k0 + c4 * 4];
        putB(sB, n, c4 * 4 + 0, v.x); putB(sB, n, c4 * 4 + 1, v.y);
        putB(sB, n, c4 * 4 + 2, v.z); putB(sB, n, c4 * 4 + 3, v.w);
    }
}

__device__ __forceinline__ void stage_A_node(uint32_t* sA, const float* __restrict__ X,
                                             int m0, int k0) {
    int tid = threadIdx.x;
#pragma unroll
    for (int i = 0; i < 4; i++) {
        int id = tid + 256 * i;
        int row = id >> 3, c4 = id & 7;
        int node = m0 + row;
        float4 v = make_float4(0.f, 0.f, 0.f, 0.f);
        if (node < NN) v = *(const float4*)&X[(size_t)node * DN + k0 + c4 * 4];
        putA(sA, row, c4 * 4 + 0, v.x); putA(sA, row, c4 * 4 + 1, v.y);
        putA(sA, row, c4 * 4 + 2, v.z); putA(sA, row, c4 * 4 + 3, v.w);
    }
}

__device__ __forceinline__ void stage_A_edge(uint32_t* sA, const char* smem,
                                             const float* __restrict__ ef,
                                             int e0, int c) {
    int tid = threadIdx.x;
    if (c < 2) {
        const float* sT  = (const float*)(smem + SM_T);
        const float* sW  = (const float*)(smem + SM_W);
        const float* sBt = (const float*)(smem + SM_BT);
        int k0 = c * 32;
#pragma unroll
        for (int i = 0; i < 16; i++) {
            int id = tid + 256 * i;
            int row = id >> 5, kk = id & 31;
            float v = cosf(sT[row] * sW[k0 + kk] + sBt[k0 + kk]);
            putA(sA, row, kk, v);
        }
    } else {
        int k0 = c * 32 - 64;
#pragma unroll
        for (int i = 0; i < 4; i++) {
            int id = tid + 256 * i;
            int row = id >> 3, c4 = id & 7;
            float4 v = *(const float4*)&ef[(size_t)(e0 + row) * DEF + k0 + c4 * 4];
            putA(sA, row, c4 * 4 + 0, v.x); putA(sA, row, c4 * 4 + 1, v.y);
            putA(sA, row, c4 * 4 + 2, v.z); putA(sA, row, c4 * 4 + 3, v.w);
        }
    }
}

__device__ __forceinline__ void chunk_mma(const uint32_t* sA, const uint32_t* sB,
                                          int warpM, int warpN, int lane,
                                          float acc[2][8][4]) {
#pragma unroll
    for (int ks = 0; ks < 4; ks++) {
        uint32_t af[2][4];
#pragma unroll
        for (int m = 0; m < 2; m++)
            *(uint4*)af[m] = *(const uint4*)&sA[((ks * 8 + warpM * 2 + m) * 32 + lane) * 4];
        uint32_t bf[8][2];
#pragma unroll
        for (int j = 0; j < 8; j++)
            *(uint2*)bf[j] = *(const uint2*)&sB[((ks * 16 + warpN * 8 + j) * 32 + lane) * 2];
#pragma unroll
        for (int m = 0; m < 2; m++)
#pragma unroll
            for (int j = 0; j < 8; j++) mma_tf32(acc[m][j], af[m], bf[j]);
    }
}

// ---------------- K0: zero accumulators -------------------------------------
__global__ void k_init() {
    int i = blockIdx.x * blockDim.x + threadIdx.x;
    if (i < NN * DN / 4) ((float4*)g_acc)[i] = make_float4(0.f, 0.f, 0.f, 0.f);
    if (i < NN * H) g_denom[i] = 0.0f;
}

// ---------------- node GEMMs: Q,K,V,skip ------------------------------------
__global__ __launch_bounds__(256, 2)
void k_node_mma(const float* __restrict__ X,
                const float* __restrict__ Wq, const float* __restrict__ Wk,
                const float* __restrict__ Wv, const float* __restrict__ Ws,
                const float* __restrict__ bq, const float* __restrict__ bk,
                const float* __restrict__ bv, const float* __restrict__ bs,
                float* __restrict__ out) {
    extern __shared__ char smem[];
    const int tid = threadIdx.x, wid = tid >> 5, lane = tid & 31;
    const int warpM = wid & 3, warpN = wid >> 2;
    const int m0 = blockIdx.x * 128;
    const int by = blockIdx.y, mat = by >> 1, n0 = (by & 1) * 128;
    const float* W; const float* bias; float* dst;
    if      (mat == 0) { W = Wq; bias = bq; dst = g_Q; }
    else if (mat == 1) { W = Wk; bias = bk; dst = g_K; }
    else if (mat == 2) { W = Wv; bias = bv; dst = g_V; }
    else               { W = Ws; bias = bs; dst = out; }

    uint32_t* sA[2] = { (uint32_t*)(smem + SM_A0), (uint32_t*)(smem + SM_A1) };
    uint32_t* sB[2] = { (uint32_t*)(smem + SM_B0), (uint32_t*)(smem + SM_B1) };

    float acc[2][8][4] = {};

    stage_A_node(sA[0], X, m0, 0);
    stage_B_w(sB[0], W, n0, 0, DN);
    __syncthreads();

    for (int c = 0; c < 8; c++) {
        chunk_mma(sA[c & 1], sB[c & 1], warpM, warpN, lane, acc);
        if (c < 7) {
            stage_A_node(sA[(c + 1) & 1], X, m0, (c + 1) * 32);
            stage_B_w(sB[(c + 1) & 1], W, n0, (c + 1) * 32, DN);
        }
        __syncthreads();
    }

    float2 bb[8];
#pragma unroll
    for (int j = 0; j < 8; j++)
        bb[j] = *(const float2*)&bias[n0 + warpN * 64 + j * 8 + (lane & 3) * 2];
#pragma unroll
    for (int m = 0; m < 2; m++)
#pragma unroll
        for (int rv = 0; rv < 2; rv++) {
            int node = m0 + warpM * 32 + m * 16 + rv * 8 + (lane >> 2);
            if (node >= NN) continue;
            float* dp = dst + (size_t)node * DN + n0 + warpN * 64 + (lane & 3) * 2;
#pragma unroll
            for (int j = 0; j < 8; j++) {
                float2 o = make_float2(acc[m][j][rv * 2 + 0] + bb[j].x,
                                       acc[m][j][rv * 2 + 1] + bb[j].y);
                *(float2*)(dp + j * 8) = o;
            }
        }
}

// ------- edge GEMM + fused time-enc + alpha + exp + scatter-aggregate -------
__global__ __launch_bounds__(256, 2)
void k_edge_mma(const float* __restrict__ ef, const int* __restrict__ etup,
                const float* __restrict__ We, const float* __restrict__ times,
                const float* __restrict__ wt, const float* __restrict__ bt) {
    extern __shared__ char smem[];
    const int tid = threadIdx.x, wid = tid >> 5, lane = tid & 31;
    const int warpM = wid & 3, warpN = wid >> 2;
    const int e0 = blockIdx.x * 128;
    const int n0 = blockIdx.y * 128;

    if (tid < 128) ((float*)(smem + SM_T))[tid] = times[e0 + tid];
    if (tid < 64) {
        ((float*)(smem + SM_W))[tid]  = wt[tid];
        ((float*)(smem + SM_BT))[tid] = bt[tid];
    }
    __syncthreads();

    uint32_t* sA[2] = { (uint32_t*)(smem + SM_A0), (uint32_t*)(smem + SM_A1) };
    uint32_t* sB[2] = { (uint32_t*)(smem + SM_B0), (uint32_t*)(smem + SM_B1) };

    float acc[2][8][4] = {};

    stage_A_edge(sA[0], smem, ef, e0, 0);
    stage_B_w(sB[0], We, n0, 0, DEIN);
    __syncthreads();

    for (int c = 0; c < 6; c++) {
        chunk_mma(sA[c & 1], sB[c & 1], warpM, warpN, lane, acc);
        if (c < 5) {
            stage_A_edge(sA[(c + 1) & 1], smem, ef, e0, c + 1);
            stage_B_w(sB[(c + 1) & 1], We, n0, (c + 1) * 32, DEIN);
        }
        __syncthreads();
    }

    // epilogue: alpha per head, w = exp(alpha), scatter w*(v+ep) and denom
    const float scale = 0.17677669529663687f;   // 1/sqrt(32)
    const int coloff = n0 + warpN * 64 + (lane & 3) * 2;
    const int hb = (n0 + warpN * 64) >> 5;      // head for j<4; hb+1 for j>=4
#pragma unroll
    for (int m = 0; m < 2; m++)
#pragma unroll
        for (int rv = 0; rv < 2; rv++) {
            int e = e0 + warpM * 32 + m * 16 + rv * 8 + (lane >> 2);
            int s = etup[e];
            int d = etup[EE + e];
            const float* qrow = g_Q + (size_t)d * DN + coloff;
            const float* krow = g_K + (size_t)s * DN + coloff;
            const float* vrow = g_V + (size_t)s * DN + coloff;
            float* arow = g_acc + (size_t)d * DN + coloff;

            float p0 = 0.f, p1 = 0.f;
            float2 vv[8];
#pragma unroll
            for (int j = 0; j < 8; j++) {
                float c0 = acc[m][j][rv * 2 + 0];
                float c1 = acc[m][j][rv * 2 + 1];
                float2 qv = *(const float2*)(qrow + j * 8);
                float2 kv = *(const float2*)(krow + j * 8);
                vv[j] = *(const float2*)(vrow + j * 8);
                float p = qv.x * (kv.x + c0) + qv.y * (kv.y + c1);
                if (j < 4) p0 += p; else p1 += p;
            }
            p0 += __shfl_xor_sync(0xffffffffu, p0, 1);
            p0 += __shfl_xor_sync(0xffffffffu, p0, 2);
            p1 += __shfl_xor_sync(0xffffffffu, p1, 1);
            p1 += __shfl_xor_sync(0xffffffffu, p1, 2);
            float w0 = __expf(p0 * scale);
            float w1 = __expf(p1 * scale);
#pragma unroll
            for (int j = 0; j < 8; j++) {
                float w = (j < 4) ? w0 : w1;
                float2 r = make_float2(w * (vv[j].x + acc[m][j][rv * 2 + 0]),
                                       w * (vv[j].y + acc[m][j][rv * 2 + 1]));
                red_add_v2(arow + j * 8, r);
            }
            if ((lane & 3) == 0) {
                red_add_f(&g_denom[d * H + hb],     w0);
                red_add_f(&g_denom[d * H + hb + 1], w1);
            }
        }
}

// ---------------- finalize: out = skip + acc/denom ---------------------------
__global__ __launch_bounds__(256)
void k_finalize(float* __restrict__ out) {
    int idx = blockIdx.x * blockDim.x + threadIdx.x;   // one float4 per thread
    if (idx >= NN * DN / 4) return;
    int node = idx >> 6;
    int col4 = idx & 63;
    int head = col4 >> 3;
    float den = g_denom[node * H + head] + 1e-16f;
    float inv = 1.0f / den;
    float4 a = ((const float4*)g_acc)[idx];
    float4 o = ((float4*)out)[idx];
    o.x += a.x * inv; o.y += a.y * inv; o.z += a.z * inv; o.w += a.w * inv;
    ((float4*)out)[idx] = o;
}

// ---------------- launch ----------------------------------------------------
extern "C" void kernel_launch(void* const* d_in, const int* in_sizes, int n_in,
                              void* d_out, int out_size) {
    const int*   etup       = (const int*)  d_in[0];
    const float* edge_feats = (const float*)d_in[1];
    const float* times      = (const float*)d_in[2];
    const float* X          = (const float*)d_in[3];
    const float* w_time     = (const float*)d_in[4];
    const float* b_time     = (const float*)d_in[5];
    const float* Wq         = (const float*)d_in[6];
    const float* bq         = (const float*)d_in[7];
    const float* Wk         = (const float*)d_in[8];
    const float* bk         = (const float*)d_in[9];
    const float* Wv         = (const float*)d_in[10];
    const float* bv         = (const float*)d_in[11];
    const float* We         = (const float*)d_in[12];
    const float* Ws         = (const float*)d_in[13];
    const float* bs         = (const float*)d_in[14];
    float* out = (float*)d_out;

    cudaFuncSetAttribute(k_node_mma, cudaFuncAttributeMaxDynamicSharedMemorySize, SMEM_BYTES);
    cudaFuncSetAttribute(k_edge_mma, cudaFuncAttributeMaxDynamicSharedMemorySize, SMEM_BYTES);

    k_init<<<(NN * DN / 4 + 255) / 256, 256>>>();
    k_node_mma<<<dim3((NN + 127) / 128, 8), 256, SMEM_BYTES>>>(
        X, Wq, Wk, Wv, Ws, bq, bk, bv, bs, out);
    k_edge_mma<<<dim3(EE / 128, 2), 256, SMEM_BYTES>>>(
        edge_feats, etup, We, times, w_time, b_time);
    k_finalize<<<(NN * DN / 4 + 255) / 256, 256>>>(out);
}